// round 5
// baseline (speedup 1.0000x reference)
#include <cuda_runtime.h>
#include <cuda_fp16.h>
#include <cstdint>

#define TT 256
#define BB 512
#define FF 64
#define UU 128
#define NG 512           // 4*U
#define TB (TT*BB)       // 131072

// ---------- static device scratch (no allocation) ----------
__device__ float  g_xz [(size_t)TB * NG];   // xz scratch fp32 (reused both layers)
__device__ __half g_hs [(size_t)TB * UU];   // layer-1 hidden states [t][b][u]
__device__ float  g_hlast[BB * UU];         // layer-2 final h

// ---------- helpers ----------
__device__ __forceinline__ void mma16816(float* d, const uint32_t* a, uint32_t b0, uint32_t b1) {
    asm volatile(
        "mma.sync.aligned.m16n8k16.row.col.f32.f16.f16.f32 "
        "{%0,%1,%2,%3}, {%4,%5,%6,%7}, {%8,%9}, {%0,%1,%2,%3};"
        : "+f"(d[0]), "+f"(d[1]), "+f"(d[2]), "+f"(d[3])
        : "r"(a[0]), "r"(a[1]), "r"(a[2]), "r"(a[3]), "r"(b0), "r"(b1));
}
__device__ __forceinline__ void ldsm4(uint32_t* a, const __half* p) {
    uint32_t addr = (uint32_t)__cvta_generic_to_shared(p);
    asm volatile("ldmatrix.sync.aligned.m8n8.x4.shared.b16 {%0,%1,%2,%3}, [%4];"
                 : "=r"(a[0]), "=r"(a[1]), "=r"(a[2]), "=r"(a[3]) : "r"(addr));
}
__device__ __forceinline__ float tanha(float x) {
    float r;
    asm("tanh.approx.f32 %0, %1;" : "=f"(r) : "f"(x));
    return r;
}
__device__ __forceinline__ float sigm(float x) {
    return fmaf(0.5f, tanha(0.5f * x), 0.5f);
}

// ---------- GEMM: out[M][512] = A @ W(fp32->fp16) + bias ----------
// DX=true: A is raw x fp32 [b][t][f], converted during staging (K=64).
// DX=false: A is fp16 row-major [M][K].
template <int K, int NT, bool DX>
__global__ void __launch_bounds__(256, 2)
k_gemm(const void* __restrict__ Av, const float* __restrict__ Wg,
       const float* __restrict__ bias, float* __restrict__ out, int Mtiles) {
    extern __shared__ char sm[];
    const int LDW = NT + 8;
    uint32_t* Wp = (uint32_t*)sm;                                // [K/2][LDW] half2
    __half*   As = (__half*)(sm + (K / 2) * LDW * 4);            // [64][K+8]
    const int ldA = K + 8;
    const int NS = 512 / NT;
    int tid = threadIdx.x, w = tid >> 5, lane = tid & 31;
    int n0 = (blockIdx.x % NS) * NT;

    for (int i = tid; i < (K / 2) * NT; i += 256) {
        int kk = i / NT, nl = i % NT, n = n0 + nl;
        __half2 h2 = __floats2half2_rn(Wg[(size_t)(2 * kk) * NG + n],
                                       Wg[(size_t)(2 * kk + 1) * NG + n]);
        Wp[kk * LDW + nl] = *(uint32_t*)&h2;
    }

    for (int tile = blockIdx.x / NS; tile < Mtiles; tile += gridDim.x / NS) {
        int m0 = tile * 64;
        __syncthreads();
        if (DX) {
            // rows m = t*BB + b ; x layout [b][t][f]
            const float* X = (const float*)Av;
            for (int i = tid; i < 64 * (K / 4); i += 256) {
                int r = i / (K / 4), c = (i % (K / 4)) * 4;
                int m = m0 + r, t = m >> 9, b = m & 511;
                float4 v = *(const float4*)&X[((size_t)(b << 8 | t)) * FF + c];
                __half2 h01 = __floats2half2_rn(v.x, v.y);
                __half2 h23 = __floats2half2_rn(v.z, v.w);
                *(__half2*)&As[r * ldA + c] = h01;
                *(__half2*)&As[r * ldA + c + 2] = h23;
            }
        } else {
            const __half* A = (const __half*)Av;
            for (int i = tid; i < 64 * (K / 8); i += 256) {
                int r = i / (K / 8), c = (i % (K / 8)) * 8;
                *(uint4*)&As[r * ldA + c] = *(const uint4*)&A[(size_t)(m0 + r) * K + c];
            }
        }
        __syncthreads();

        float acc[4][NT / 64][4];
#pragma unroll
        for (int mt = 0; mt < 4; mt++)
#pragma unroll
            for (int nt = 0; nt < NT / 64; nt++)
#pragma unroll
                for (int q = 0; q < 4; q++) acc[mt][nt][q] = 0.f;

#pragma unroll
        for (int kt = 0; kt < K / 16; kt++) {
            uint32_t a[4][4];
#pragma unroll
            for (int mt = 0; mt < 4; mt++) {
                int row = mt * 16 + (lane & 15);
                int col = kt * 16 + (lane >> 4) * 8;
                ldsm4(a[mt], &As[row * ldA + col]);
            }
            int c4 = lane & 3;
#pragma unroll
            for (int nt = 0; nt < NT / 64; nt++) {
                int nl = w * (NT / 8) + nt * 8 + (lane >> 2);
                uint32_t b0 = Wp[(kt * 8 + c4) * LDW + nl];
                uint32_t b1 = Wp[(kt * 8 + 4 + c4) * LDW + nl];
#pragma unroll
                for (int mt = 0; mt < 4; mt++) mma16816(acc[mt][nt], a[mt], b0, b1);
            }
        }
#pragma unroll
        for (int mt = 0; mt < 4; mt++) {
            int r0 = m0 + mt * 16 + (lane >> 2);
#pragma unroll
            for (int nt = 0; nt < NT / 64; nt++) {
                int cc = n0 + w * (NT / 8) + nt * 8 + (lane & 3) * 2;
                float bb0 = __ldg(&bias[cc]), bb1 = __ldg(&bias[cc + 1]);
                *(float2*)&out[(size_t)r0 * NG + cc] =
                    make_float2(acc[mt][nt][0] + bb0, acc[mt][nt][1] + bb1);
                *(float2*)&out[(size_t)(r0 + 8) * NG + cc] =
                    make_float2(acc[mt][nt][2] + bb0, acc[mt][nt][3] + bb1);
            }
        }
    }
}

// ---------- LSTM recurrence, cluster-2 M-split ----------
// 64 clusters x 8 batches; CTA rank owns units [rank*64, rank*64+64) x 4 gates.
// Warp w: units w*8..w*8+7; m16-tile mt: gates {2mt, 2mt+1}. C-frag = 1 unit x
// 2 batches per thread -> zero shuffles. h exchanged each step via DSMEM +
// one 512-arrival cluster mbarrier.
template <int LAYER>
__global__ void __launch_bounds__(256, 1) __cluster_dims__(2, 1, 1)
k_rnn(const float* __restrict__ Urec) {
    extern __shared__ char sm[];
    __half* As = (__half*)sm;                               // [256][136] staging
    char*   hpbase = sm + 256 * 136 * 2;                    // 2 phases x 2048 B
    uint64_t* mbar = (uint64_t*)(hpbase + 4096);
    const int th = threadIdx.x, w = th >> 5, lane = th & 31;
    uint32_t rank;
    asm("mov.u32 %0, %%cluster_ctarank;" : "=r"(rank));
    const int b0 = (blockIdx.x >> 1) * 8;

    // stage permuted U^T rows: row = w*32 + mt*16 + sub*8 + r
    // -> gate = 2mt+sub, global col G = gate*128 + rank*64 + w*8 + r
    for (int i = th; i < 256 * 128; i += 256) {
        int row = i >> 7, k = i & 127;
        int ww = row >> 5, mt = (row >> 4) & 1, sub = (row >> 3) & 1, r = row & 7;
        int G = (mt * 2 + sub) * 128 + rank * 64 + ww * 8 + r;
        As[row * 136 + k] = __float2half(Urec[(size_t)k * NG + G]);
    }
    for (int i = th; i < 1024; i += 256) ((uint32_t*)hpbase)[i] = 0u;
    if (th == 0) {
        uint32_t mb = (uint32_t)__cvta_generic_to_shared(mbar);
        asm volatile("mbarrier.init.shared.b64 [%0], 512;" :: "r"(mb) : "memory");
    }
    __syncthreads();

    uint32_t ua[2][8][4];
#pragma unroll
    for (int mt = 0; mt < 2; mt++) {
        int row = w * 32 + mt * 16 + (lane & 15);
#pragma unroll
        for (int kt = 0; kt < 8; kt++)
            ldsm4(ua[mt][kt], &As[row * 136 + kt * 16 + (lane >> 4) * 8]);
    }
    // cluster barrier: peers' mbar init + hp zero visible before any remote op
    asm volatile("barrier.cluster.arrive.aligned;" ::: "memory");
    asm volatile("barrier.cluster.wait.aligned;" ::: "memory");

    const int r8 = lane >> 2;            // unit offset in warp
    const int q  = lane & 3;             // batch-pair
    const int u  = rank * 64 + w * 8 + r8;   // this thread's global unit
    const int j0 = 2 * q;
    // writer target offsets into hp (byte): per (j)
    const int ktw = u >> 4, kuw = u & 15;
    const int wbase = ktw * 256 + ((kuw >> 1) & 3) * 8 + ((kuw >> 3) & 1) * 4 + (kuw & 1) * 2;
    uint32_t mb_local = (uint32_t)__cvta_generic_to_shared(mbar);
    uint32_t mb_peer, hp_peer_u32;
    asm("mapa.shared::cluster.u32 %0, %1, %2;" : "=r"(mb_peer) : "r"(mb_local), "r"(rank ^ 1));
    {
        uint32_t hp_local = (uint32_t)__cvta_generic_to_shared(hpbase);
        asm("mapa.shared::cluster.u32 %0, %1, %2;" : "=r"(hp_peer_u32) : "r"(hp_local), "r"(rank ^ 1));
    }

    float xc[4][2];
    {
        const float* p = g_xz + ((size_t)(b0 + j0)) * NG + u;
#pragma unroll
        for (int g = 0; g < 4; g++) { xc[g][0] = __ldg(p + g * 128); xc[g][1] = __ldg(p + NG + g * 128); }
    }
    float cst[2] = {0.f, 0.f};
    int ph = 0, par = 0;

    for (int t = 0; t < TT; t++) {
        // prefetch next xz early (independent)
        float xn[4][2];
        if (t + 1 < TT) {
            const float* p = g_xz + ((size_t)(t + 1) * BB + b0 + j0) * NG + u;
#pragma unroll
            for (int g = 0; g < 4; g++) { xn[g][0] = __ldg(p + g * 128); xn[g][1] = __ldg(p + NG + g * 128); }
        }
        // ---- mma: z = U^T_half @ h^T  (reads hp[ph], packed B-frags) ----
        float acc[2][4];
#pragma unroll
        for (int mt = 0; mt < 2; mt++)
#pragma unroll
            for (int qq = 0; qq < 4; qq++) acc[mt][qq] = 0.f;
        const uint2* hb = (const uint2*)(hpbase + ph * 2048);
#pragma unroll
        for (int kt = 0; kt < 8; kt++) {
            uint2 bf = hb[kt * 32 + lane];
#pragma unroll
            for (int mt = 0; mt < 2; mt++) mma16816(acc[mt], ua[mt][kt], bf.x, bf.y);
        }

        // ---- elementwise: acc[0]={i(j0),i(j1),f(j0),f(j1)}, acc[1]={g,g,o,o} ----
        char* hpn_l = hpbase + (ph ^ 1) * 2048;
        uint32_t hpn_p = hp_peer_u32 + (ph ^ 1) * 2048;
#pragma unroll
        for (int j = 0; j < 2; j++) {
            float iv = sigm(acc[0][j] + xc[0][j]);
            float fv = sigm(acc[0][2 + j] + xc[1][j]);
            float gv = tanha(acc[1][j] + xc[2][j]);
            float ov = sigm(acc[1][2 + j] + xc[3][j]);
            cst[j] = fv * cst[j] + iv * gv;
            float hv = ov * tanha(cst[j]);
            int bj = j0 + j;
            __half hh = __float2half(hv);
            if (t + 1 < TT) {
                int off = wbase + bj * 8 + ((bj >> 1) - q) * 0; // wbase + j*... (n = bj)
                // byte offset: kt*256 + (n*4 + c4)*8 + wsel*4 + hb*2  == wbase + bj*32? no:
                // recompute exactly: (bj*4 + c4)*8 = bj*32 + c4*8 ; wbase already has c4*8
                off = ktw * 256 + bj * 32 + ((kuw >> 1) & 3) * 8 + ((kuw >> 3) & 1) * 4 + (kuw & 1) * 2;
                *(__half*)(hpn_l + off) = hh;
                uint16_t hraw = *(uint16_t*)&hh;
                asm volatile("st.shared::cluster.u16 [%0], %1;" :: "r"(hpn_p + off), "h"(hraw) : "memory");
            }
            if (LAYER == 0) {
                g_hs[((size_t)t * BB + b0 + bj) * UU + u] = hh;
            } else if (t == TT - 1) {
                g_hlast[(size_t)(b0 + bj) * UU + u] = hv;
            }
        }
#pragma unroll
        for (int g = 0; g < 4; g++) { xc[g][0] = xn[g][0]; xc[g][1] = xn[g][1]; }

        if (t + 1 < TT) {
            // arrive local (release cluster) + peer, then wait local
            asm volatile("mbarrier.arrive.release.cluster.shared::cta.b64 _, [%0];"
                         :: "r"(mb_local) : "memory");
            asm volatile("mbarrier.arrive.release.cluster.shared::cluster.b64 _, [%0];"
                         :: "r"(mb_peer) : "memory");
            {
                uint32_t done;
                asm volatile(
                    "{\n\t.reg .pred p;\n\t"
                    "mbarrier.try_wait.parity.acquire.cluster.shared::cta.b64 p, [%1], %2;\n\t"
                    "selp.b32 %0, 1, 0, p;\n\t}"
                    : "=r"(done) : "r"(mb_local), "r"(par) : "memory");
                if (!done) {
                    asm volatile(
                        "{\n\t.reg .pred P1;\n\t"
                        "W%=:\n\t"
                        "mbarrier.try_wait.parity.acquire.cluster.shared::cta.b64 P1, [%0], %1, 0x989680;\n\t"
                        "@P1 bra.uni D%=;\n\t"
                        "bra.uni W%=;\n\t"
                        "D%=:\n\t}"
                        :: "r"(mb_local), "r"(par) : "memory");
                }
            }
            par ^= 1;
            ph ^= 1;
        }
    }
    asm volatile("barrier.cluster.arrive.aligned;" ::: "memory");
    asm volatile("barrier.cluster.wait.aligned;" ::: "memory");
}

// ---------- dense ----------
__global__ void k_dense(const float* __restrict__ Wd, const float* __restrict__ bd,
                        float* __restrict__ out) {
    int b = blockIdx.x * blockDim.x + threadIdx.x;
    if (b >= BB) return;
    float acc = bd[0];
    const float* h = &g_hlast[(size_t)b * UU];
#pragma unroll 8
    for (int u = 0; u < UU; u++) acc = fmaf(h[u], Wd[u], acc);
    out[b] = fmaxf(acc, 0.f);
}

// ---------- launch ----------
extern "C" void kernel_launch(void* const* d_in, const int* in_sizes, int n_in,
                              void* d_out, int out_size) {
    const float* x  = (const float*)d_in[0];
    const float* W1 = (const float*)d_in[1];
    const float* U1 = (const float*)d_in[2];
    const float* b1 = (const float*)d_in[3];
    const float* W2 = (const float*)d_in[4];
    const float* U2 = (const float*)d_in[5];
    const float* b2 = (const float*)d_in[6];
    const float* Wd = (const float*)d_in[7];
    const float* bd = (const float*)d_in[8];
    float* out = (float*)d_out;

    const int SM_G64  = 32 * 264 * 4 + 64 * 72 * 2;          // 43008
    const int SM_G128 = 64 * 264 * 4 + 64 * 136 * 2;         // 84992
    const int SM_RNN  = 256 * 136 * 2 + 4096 + 64;           // 73792

    cudaFuncSetAttribute((const void*)k_gemm<64, 256, true>,
                         cudaFuncAttributeMaxDynamicSharedMemorySize, SM_G64);
    cudaFuncSetAttribute((const void*)k_gemm<128, 256, false>,
                         cudaFuncAttributeMaxDynamicSharedMemorySize, SM_G128);
    cudaFuncSetAttribute((const void*)k_rnn<0>,
                         cudaFuncAttributeMaxDynamicSharedMemorySize, SM_RNN);
    cudaFuncSetAttribute((const void*)k_rnn<1>,
                         cudaFuncAttributeMaxDynamicSharedMemorySize, SM_RNN);

    float*  xzp;   cudaGetSymbolAddress((void**)&xzp,  g_xz);
    __half* hsp;   cudaGetSymbolAddress((void**)&hsp,  g_hs);

    k_gemm<64, 256, true><<<296, 256, SM_G64>>>(x, W1, b1, xzp, TB / 64);
    k_rnn<0><<<128, 256, SM_RNN>>>(U1);
    k_gemm<128, 256, false><<<296, 256, SM_G128>>>(hsp, W2, b2, xzp, TB / 64);
    k_rnn<1><<<128, 256, SM_RNN>>>(U2);
    k_dense<<<4, 128>>>(Wd, bd, out);
}

// round 7
// speedup vs baseline: 1.3910x; 1.3910x over previous
#include <cuda_runtime.h>
#include <cuda_fp16.h>
#include <cstdint>

#define TT 256
#define BB 512
#define FF 64
#define UU 128
#define NG 512           // 4*U
#define TB (TT*BB)       // 131072

// ---------- static device scratch (no allocation) ----------
__device__ float  g_xz [(size_t)TB * NG];   // xz scratch fp32 (reused both layers)
__device__ __half g_hs [(size_t)TB * UU];   // layer-1 hidden states [t][b][u]
__device__ float  g_hlast[BB * UU];         // layer-2 final h

// ---------- helpers ----------
__device__ __forceinline__ void mma16816(float* d, const uint32_t* a, uint32_t b0, uint32_t b1) {
    asm volatile(
        "mma.sync.aligned.m16n8k16.row.col.f32.f16.f16.f32 "
        "{%0,%1,%2,%3}, {%4,%5,%6,%7}, {%8,%9}, {%0,%1,%2,%3};"
        : "+f"(d[0]), "+f"(d[1]), "+f"(d[2]), "+f"(d[3])
        : "r"(a[0]), "r"(a[1]), "r"(a[2]), "r"(a[3]), "r"(b0), "r"(b1));
}
__device__ __forceinline__ void ldsm4(uint32_t* a, const __half* p) {
    uint32_t addr = (uint32_t)__cvta_generic_to_shared(p);
    asm volatile("ldmatrix.sync.aligned.m8n8.x4.shared.b16 {%0,%1,%2,%3}, [%4];"
                 : "=r"(a[0]), "=r"(a[1]), "=r"(a[2]), "=r"(a[3]) : "r"(addr));
}
__device__ __forceinline__ float tanha(float x) {
    float r;
    asm("tanh.approx.f32 %0, %1;" : "=f"(r) : "f"(x));
    return r;
}
__device__ __forceinline__ float sigm(float x) {
    return fmaf(0.5f, tanha(0.5f * x), 0.5f);
}

// ---------- GEMM: out[M][512] = A @ W(fp32->fp16) + bias ----------
// DX=true: A is raw x fp32 [b][t][f], converted during staging (K=64).
template <int K, int NT, bool DX>
__global__ void __launch_bounds__(256, 2)
k_gemm(const void* __restrict__ Av, const float* __restrict__ Wg,
       const float* __restrict__ bias, float* __restrict__ out, int Mtiles) {
    extern __shared__ char sm[];
    const int LDW = NT + 8;
    uint32_t* Wp = (uint32_t*)sm;                                // [K/2][LDW] half2
    __half*   As = (__half*)(sm + (K / 2) * LDW * 4);            // [64][K+8]
    const int ldA = K + 8;
    const int NS = 512 / NT;
    int tid = threadIdx.x, w = tid >> 5, lane = tid & 31;
    int n0 = (blockIdx.x % NS) * NT;

    for (int i = tid; i < (K / 2) * NT; i += 256) {
        int kk = i / NT, nl = i % NT, n = n0 + nl;
        __half2 h2 = __floats2half2_rn(Wg[(size_t)(2 * kk) * NG + n],
                                       Wg[(size_t)(2 * kk + 1) * NG + n]);
        Wp[kk * LDW + nl] = *(uint32_t*)&h2;
    }

    for (int tile = blockIdx.x / NS; tile < Mtiles; tile += gridDim.x / NS) {
        int m0 = tile * 64;
        __syncthreads();
        if (DX) {
            const float* X = (const float*)Av;
            for (int i = tid; i < 64 * (K / 4); i += 256) {
                int r = i / (K / 4), c = (i % (K / 4)) * 4;
                int m = m0 + r, t = m >> 9, b = m & 511;
                float4 v = *(const float4*)&X[((size_t)(b << 8 | t)) * FF + c];
                *(__half2*)&As[r * ldA + c]     = __floats2half2_rn(v.x, v.y);
                *(__half2*)&As[r * ldA + c + 2] = __floats2half2_rn(v.z, v.w);
            }
        } else {
            const __half* A = (const __half*)Av;
            for (int i = tid; i < 64 * (K / 8); i += 256) {
                int r = i / (K / 8), c = (i % (K / 8)) * 8;
                *(uint4*)&As[r * ldA + c] = *(const uint4*)&A[(size_t)(m0 + r) * K + c];
            }
        }
        __syncthreads();

        float acc[4][NT / 64][4];
#pragma unroll
        for (int mt = 0; mt < 4; mt++)
#pragma unroll
            for (int nt = 0; nt < NT / 64; nt++)
#pragma unroll
                for (int q = 0; q < 4; q++) acc[mt][nt][q] = 0.f;

#pragma unroll
        for (int kt = 0; kt < K / 16; kt++) {
            uint32_t a[4][4];
#pragma unroll
            for (int mt = 0; mt < 4; mt++) {
                int row = mt * 16 + (lane & 15);
                int col = kt * 16 + (lane >> 4) * 8;
                ldsm4(a[mt], &As[row * ldA + col]);
            }
            int c4 = lane & 3;
#pragma unroll
            for (int nt = 0; nt < NT / 64; nt++) {
                int nl = w * (NT / 8) + nt * 8 + (lane >> 2);
                uint32_t b0 = Wp[(kt * 8 + c4) * LDW + nl];
                uint32_t b1 = Wp[(kt * 8 + 4 + c4) * LDW + nl];
#pragma unroll
                for (int mt = 0; mt < 4; mt++) mma16816(acc[mt][nt], a[mt], b0, b1);
            }
        }
#pragma unroll
        for (int mt = 0; mt < 4; mt++) {
            int r0 = m0 + mt * 16 + (lane >> 2);
#pragma unroll
            for (int nt = 0; nt < NT / 64; nt++) {
                int cc = n0 + w * (NT / 8) + nt * 8 + (lane & 3) * 2;
                float bb0 = __ldg(&bias[cc]), bb1 = __ldg(&bias[cc + 1]);
                *(float2*)&out[(size_t)r0 * NG + cc] =
                    make_float2(acc[mt][nt][0] + bb0, acc[mt][nt][1] + bb1);
                *(float2*)&out[(size_t)(r0 + 8) * NG + cc] =
                    make_float2(acc[mt][nt][2] + bb0, acc[mt][nt][3] + bb1);
            }
        }
    }
}

// ---------- LSTM recurrence ----------
// 128 CTAs x 4 batches. Warp w owns units [w*16, w*16+16). Tile mt:
//   unit-octet ug = mt>>1, gate-pair gp = mt&1; rows: sub*8+r -> gate 2gp+sub,
//   unit w*16 + ug*8 + r. C-frag: lane (r8=lane>>2, q=lane&3) tile mt holds
//   gates {2gp, 2gp+1} of unit w*16+ug*8+r8, batches 2q, 2q+1 (q<2 valid).
// 8x shfl.xor(2) moves unit-octet-1 data to lanes q>=2 -> all lanes do 2 cells.
// hp: double-buffered B-fragments as uint2 (bf0|bf1), ONE barrier per step.
template <int LAYER>
__global__ void __launch_bounds__(256, 1)
k_rnn(const float* __restrict__ Urec) {
    extern __shared__ char sm[];
    __half* As = (__half*)sm;                        // [512][136] = 139264 B
    char*   hp = sm + 512 * 136 * 2;                 // 2 phases x 2048 B
    const int th = threadIdx.x, w = th >> 5, lane = th & 31;
    const int b0 = blockIdx.x * 4;

    // stage permuted U^T: row = w*64 + mt*16 + sub*8 + r
    //   -> G = (2*(mt&1)+sub)*128 + w*16 + (mt>>1)*8 + r
    for (int i = th; i < 512 * 128; i += 256) {
        int row = i >> 7, k = i & 127;
        int ww = row >> 6, mt = (row >> 4) & 3, sub = (row >> 3) & 1, r = row & 7;
        int G = (2 * (mt & 1) + sub) * 128 + ww * 16 + ((mt >> 1) & 1) * 8 + r;
        As[row * 136 + k] = __float2half(Urec[(size_t)k * NG + G]);
    }
    for (int i = th; i < 1024; i += 256) ((uint32_t*)hp)[i] = 0u;
    __syncthreads();

    // preload A fragments (static across all steps): ua[mt][kt][4]
    uint32_t ua[4][8][4];
#pragma unroll
    for (int mt = 0; mt < 4; mt++) {
        int row = w * 64 + mt * 16 + (lane & 15);
#pragma unroll
        for (int kt = 0; kt < 8; kt++)
            ldsm4(ua[mt][kt], &As[row * 136 + kt * 16 + (lane >> 4) * 8]);
    }
    __syncthreads();

    const int q  = lane & 3, r8 = lane >> 2;
    const int ug = q >> 1;               // unit-octet after exchange
    const int bp = q & 1;                // batch-pair after exchange
    const int ut = w * 16 + ug * 8 + r8; // this thread's unit
    // hp byte offset for (unit u, batch b):
    //   ((u>>4)*4 + ((u&7)>>1))*64 + b*8 + ((u>>3)&1)*4 + (u&1)*2
    const int hbase = (((ut >> 4) * 4 + ((ut & 7) >> 1)) << 6) + (((ut >> 3) & 1) << 2) + ((ut & 1) << 1);

    // current-step xz: xc[gate][jj], batches b0+2bp+jj at unit ut
    float xc[4][2];
    {
        const float* p = g_xz + ((size_t)(b0 + 2 * bp)) * NG + ut;
#pragma unroll
        for (int g = 0; g < 4; g++) { xc[g][0] = __ldg(p + g * 128); xc[g][1] = __ldg(p + NG + g * 128); }
    }
    float cst[2] = {0.f, 0.f};
    int ph = 0;

    for (int t = 0; t < TT; t++) {
        // ---- mma: z = U^T @ h^T (reads hp[ph]) ----
        float acc[4][4];
#pragma unroll
        for (int mt = 0; mt < 4; mt++)
#pragma unroll
            for (int j = 0; j < 4; j++) acc[mt][j] = 0.f;
        const char* hpc = hp + ph * 2048;
#pragma unroll
        for (int kt = 0; kt < 8; kt++) {
            uint2 bf = *(const uint2*)(hpc + kt * 256 + (lane & 3) * 64 + (lane >> 2) * 8);
#pragma unroll
            for (int mt = 0; mt < 4; mt++) mma16816(acc[mt], ua[mt][kt], bf.x, bf.y);
        }

        // prefetch next step's xz (overlaps exchange + elementwise)
        float xn[4][2];
        if (t + 1 < TT) {
            const float* p = g_xz + ((size_t)(t + 1) * BB + b0 + 2 * bp) * NG + ut;
#pragma unroll
            for (int g = 0; g < 4; g++) { xn[g][0] = __ldg(p + g * 128); xn[g][1] = __ldg(p + NG + g * 128); }
        }

        // ---- exchange: 8 shfl.xor(2); lanes q>=2 take unit-octet-1 data ----
        float e0[4], e1[4];
#pragma unroll
        for (int j = 0; j < 4; j++) {
            float t2 = __shfl_xor_sync(0xffffffffu, acc[2][j], 2);
            float t3 = __shfl_xor_sync(0xffffffffu, acc[3][j], 2);
            e0[j] = ug ? t2 : acc[0][j];
            e1[j] = ug ? t3 : acc[1][j];
        }
        // e0 = {i(j0), i(j1), f(j0), f(j1)}, e1 = {g, g, o, o} for unit ut

        // ---- elementwise: 2 cells per thread, all in registers ----
        char* hpn = hp + (ph ^ 1) * 2048;
#pragma unroll
        for (int j = 0; j < 2; j++) {
            float iv = sigm(e0[j] + xc[0][j]);
            float fv = sigm(e0[2 + j] + xc[1][j]);
            float gv = tanha(e1[j] + xc[2][j]);
            float ov = sigm(e1[2 + j] + xc[3][j]);
            cst[j] = fv * cst[j] + iv * gv;
            float hv = ov * tanha(cst[j]);
            int bl = 2 * bp + j;
            __half hh = __float2half(hv);
            if (t + 1 < TT) *(__half*)(hpn + hbase + bl * 8) = hh;
            if (LAYER == 0) {
                g_hs[((size_t)t * BB + b0 + bl) * UU + ut] = hh;
            } else if (t == TT - 1) {
                g_hlast[(size_t)(b0 + bl) * UU + ut] = hv;
            }
        }
#pragma unroll
        for (int g = 0; g < 4; g++) { xc[g][0] = xn[g][0]; xc[g][1] = xn[g][1]; }
        __syncthreads();   // hp[ph^1] complete for next step
        ph ^= 1;
    }
}

// ---------- dense ----------
__global__ void k_dense(const float* __restrict__ Wd, const float* __restrict__ bd,
                        float* __restrict__ out) {
    int b = blockIdx.x * blockDim.x + threadIdx.x;
    if (b >= BB) return;
    float acc = bd[0];
    const float* h = &g_hlast[(size_t)b * UU];
#pragma unroll 8
    for (int u = 0; u < UU; u++) acc = fmaf(h[u], Wd[u], acc);
    out[b] = fmaxf(acc, 0.f);
}

// ---------- launch ----------
extern "C" void kernel_launch(void* const* d_in, const int* in_sizes, int n_in,
                              void* d_out, int out_size) {
    const float* x  = (const float*)d_in[0];
    const float* W1 = (const float*)d_in[1];
    const float* U1 = (const float*)d_in[2];
    const float* b1 = (const float*)d_in[3];
    const float* W2 = (const float*)d_in[4];
    const float* U2 = (const float*)d_in[5];
    const float* b2 = (const float*)d_in[6];
    const float* Wd = (const float*)d_in[7];
    const float* bd = (const float*)d_in[8];
    float* out = (float*)d_out;

    const int SM_G64  = 32 * 264 * 4 + 64 * 72 * 2;        // 43008
    const int SM_G128 = 64 * 264 * 4 + 64 * 136 * 2;       // 84992
    const int SM_RNN  = 512 * 136 * 2 + 2 * 2048;          // 143360

    cudaFuncSetAttribute((const void*)k_gemm<64, 256, true>,
                         cudaFuncAttributeMaxDynamicSharedMemorySize, SM_G64);
    cudaFuncSetAttribute((const void*)k_gemm<128, 256, false>,
                         cudaFuncAttributeMaxDynamicSharedMemorySize, SM_G128);
    cudaFuncSetAttribute((const void*)k_rnn<0>,
                         cudaFuncAttributeMaxDynamicSharedMemorySize, SM_RNN);
    cudaFuncSetAttribute((const void*)k_rnn<1>,
                         cudaFuncAttributeMaxDynamicSharedMemorySize, SM_RNN);

    float*  xzp;   cudaGetSymbolAddress((void**)&xzp,  g_xz);
    __half* hsp;   cudaGetSymbolAddress((void**)&hsp,  g_hs);

    k_gemm<64, 256, true><<<296, 256, SM_G64>>>(x, W1, b1, xzp, TB / 64);
    k_rnn<0><<<128, 256, SM_RNN>>>(U1);
    k_gemm<128, 256, false><<<296, 256, SM_G128>>>(hsp, W2, b2, xzp, TB / 64);
    k_rnn<1><<<128, 256, SM_RNN>>>(U2);
    k_dense<<<4, 128>>>(Wd, bd, out);
}